// round 2
// baseline (speedup 1.0000x reference)
#include <cuda_runtime.h>
#include <math.h>

#define BATCH 8
#define DIMC 384
#define HEADS 6
#define HD 64
#define HIN 56
#define LQ 3136        // 56*56
#define LKV 784        // 28*28
#define EPS 1e-5f
#define SCALE 0.05103103630798288f   // 384^-0.5

// ---------------- scratch (device globals; no runtime allocation) ----------------
__device__ float g_qc[BATCH * LQ  * DIMC];
__device__ float g_kc[BATCH * LKV * DIMC];
__device__ float g_vc[BATCH * LKV * DIMC];
__device__ float g_qp[BATCH * LQ  * DIMC];
__device__ float g_kp[BATCH * LKV * DIMC];
__device__ float g_vp[BATCH * LKV * DIMC];
__device__ float g_ob[BATCH * LQ  * DIMC];

// ---------------- depthwise 3x3 conv + BN (inference) ----------------
// x: [B, 56*56, C] (channel-fastest). out: [B, Hout*Hout, C]
__global__ void dwconv_bn_kernel(const float* __restrict__ x,
                                 const float* __restrict__ wt,   // [C,1,3,3]
                                 const float* __restrict__ sc,
                                 const float* __restrict__ bb,
                                 const float* __restrict__ mn,
                                 const float* __restrict__ vr,
                                 float* __restrict__ out,
                                 int stride, int Hout)
{
    int idx = blockIdx.x * blockDim.x + threadIdx.x;
    int total = BATCH * Hout * Hout * DIMC;
    if (idx >= total) return;
    int c = idx % DIMC;
    int t = (idx / DIMC) % (Hout * Hout);
    int b = idx / (DIMC * Hout * Hout);
    int oy = t / Hout, ox = t % Hout;

    float acc = 0.f;
#pragma unroll
    for (int dy = 0; dy < 3; dy++) {
        int iy = oy * stride + dy - 1;
        if (iy < 0 || iy >= HIN) continue;
#pragma unroll
        for (int dx = 0; dx < 3; dx++) {
            int ix = ox * stride + dx - 1;
            if (ix < 0 || ix >= HIN) continue;
            acc += x[((size_t)b * LQ + iy * HIN + ix) * DIMC + c] * wt[c * 9 + dy * 3 + dx];
        }
    }
    float inv = rsqrtf(vr[c] + EPS);
    out[idx] = (acc - mn[c]) * inv * sc[c] + bb[c];
}

// ---------------- fp32 GEMM: Y[M,N] = X[M,K] @ W[N,K]^T (+bias) ----------------
// 128x128 block tile, BK=8, 256 threads, 8x8 microtile.
// Requires M % 128 == 0, N % 128 == 0, K % 8 == 0 (true for all our shapes).
__global__ void gemm128_xwT(const float* __restrict__ X,
                            const float* __restrict__ W,
                            const float* __restrict__ bias,
                            float* __restrict__ Y,
                            int M, int N, int K)
{
    __shared__ float sA[8][128];
    __shared__ float sB[8][128];

    const int bm = blockIdx.y * 128;
    const int bn = blockIdx.x * 128;
    const int tid = threadIdx.x;
    const int tx = tid & 15;
    const int ty = tid >> 4;
    const int lr = tid >> 1;            // 0..127 row within tile
    const int lk = (tid & 1) * 4;       // 0 or 4

    const float* Xp = X + (size_t)(bm + lr) * K + lk;
    const float* Wp = W + (size_t)(bn + lr) * K + lk;

    float acc[8][8];
#pragma unroll
    for (int i = 0; i < 8; i++)
#pragma unroll
        for (int j = 0; j < 8; j++) acc[i][j] = 0.f;

    for (int k0 = 0; k0 < K; k0 += 8) {
        float4 xa = *(const float4*)(Xp + k0);
        float4 wb = *(const float4*)(Wp + k0);
        __syncthreads();
        sA[lk + 0][lr] = xa.x; sA[lk + 1][lr] = xa.y; sA[lk + 2][lr] = xa.z; sA[lk + 3][lr] = xa.w;
        sB[lk + 0][lr] = wb.x; sB[lk + 1][lr] = wb.y; sB[lk + 2][lr] = wb.z; sB[lk + 3][lr] = wb.w;
        __syncthreads();
#pragma unroll
        for (int kk = 0; kk < 8; kk++) {
            float4 a0 = *(const float4*)&sA[kk][ty * 4];
            float4 a1 = *(const float4*)&sA[kk][64 + ty * 4];
            float4 b0 = *(const float4*)&sB[kk][tx * 4];
            float4 b1 = *(const float4*)&sB[kk][64 + tx * 4];
            float a[8] = {a0.x, a0.y, a0.z, a0.w, a1.x, a1.y, a1.z, a1.w};
            float bv[8] = {b0.x, b0.y, b0.z, b0.w, b1.x, b1.y, b1.z, b1.w};
#pragma unroll
            for (int i = 0; i < 8; i++)
#pragma unroll
                for (int j = 0; j < 8; j++)
                    acc[i][j] += a[i] * bv[j];
        }
    }

#pragma unroll
    for (int i = 0; i < 8; i++) {
        int r = bm + ((i < 4) ? (ty * 4 + i) : (64 + ty * 4 + i - 4));
#pragma unroll
        for (int j = 0; j < 8; j++) {
            int cc = bn + ((j < 4) ? (tx * 4 + j) : (64 + tx * 4 + j - 4));
            float val = acc[i][j];
            if (bias) val += bias[cc];
            Y[(size_t)r * N + cc] = val;
        }
    }
}

// ---------------- flash attention (fp32, online softmax) ----------------
// Q: [B, LQ, C], K/V: [B, LKV, C]; head h uses channels [h*64, h*64+64).
// grid: (LQ/64, HEADS, BATCH); 256 threads; dynamic smem.
#define PADT 68   // pad for k-major tiles (float4-aligned)
#define PADP 65   // pad for P tile (scalar access)
#define ATTN_SMEM ((3 * 64 * PADT + 64 * PADP + 3 * 64) * 4)

__global__ void attn_kernel(const float* __restrict__ Q,
                            const float* __restrict__ K,
                            const float* __restrict__ V,
                            float* __restrict__ O)
{
    extern __shared__ float smem[];
    float* sQt = smem;                   // [64][PADT]  sQt[d*PADT + r]
    float* sKt = sQt + 64 * PADT;        // [64][PADT]  sKt[d*PADT + n]
    float* sV  = sKt + 64 * PADT;        // [64][PADT]  sV [n*PADT + d]
    float* sP  = sV  + 64 * PADT;        // [64][PADP]  sP [r*PADP + n]
    float* sM  = sP  + 64 * PADP;        // [64]
    float* sL  = sM  + 64;               // [64]
    float* sC  = sL  + 64;               // [64]

    const int b = blockIdx.z, h = blockIdx.y;
    const int m0 = blockIdx.x * 64;
    const int tid = threadIdx.x;
    const int tx = tid & 15;
    const int ty = tid >> 4;

    const float* Qb = Q + ((size_t)b * LQ + m0) * DIMC + h * HD;

    for (int i = tid; i < 64 * 64; i += 256) {
        int r = i >> 6, d = i & 63;
        sQt[d * PADT + r] = Qb[(size_t)r * DIMC + d];
    }
    if (tid < 64) { sM[tid] = -1e30f; sL[tid] = 0.f; }

    float acc[4][4];
#pragma unroll
    for (int i = 0; i < 4; i++)
#pragma unroll
        for (int j = 0; j < 4; j++) acc[i][j] = 0.f;

    __syncthreads();

    for (int n0 = 0; n0 < LKV; n0 += 64) {
        const float* Kb = K + ((size_t)b * LKV + n0) * DIMC + h * HD;
        const float* Vb = V + ((size_t)b * LKV + n0) * DIMC + h * HD;
        int nvalid = LKV - n0; if (nvalid > 64) nvalid = 64;

        for (int i = tid; i < 64 * 64; i += 256) {
            int n = i >> 6, d = i & 63;
            float kv = 0.f, vv = 0.f;
            if (n < nvalid) {
                kv = Kb[(size_t)n * DIMC + d];
                vv = Vb[(size_t)n * DIMC + d];
            }
            sKt[d * PADT + n] = kv;
            sV [n * PADT + d] = vv;
        }
        __syncthreads();

        // S = Q @ K^T (4x4 microtile)
        float s[4][4];
#pragma unroll
        for (int i = 0; i < 4; i++)
#pragma unroll
            for (int j = 0; j < 4; j++) s[i][j] = 0.f;

#pragma unroll 8
        for (int d = 0; d < 64; d++) {
            float4 qv = *(const float4*)&sQt[d * PADT + ty * 4];
            float4 kv = *(const float4*)&sKt[d * PADT + tx * 4];
            float qa[4] = {qv.x, qv.y, qv.z, qv.w};
            float ka[4] = {kv.x, kv.y, kv.z, kv.w};
#pragma unroll
            for (int i = 0; i < 4; i++)
#pragma unroll
                for (int j = 0; j < 4; j++)
                    s[i][j] += qa[i] * ka[j];
        }
        // write scaled + masked scores
#pragma unroll
        for (int i = 0; i < 4; i++)
#pragma unroll
            for (int j = 0; j < 4; j++) {
                int n = tx * 4 + j;
                sP[(ty * 4 + i) * PADP + n] = (n < nvalid) ? s[i][j] * SCALE : -1e30f;
            }
        __syncthreads();

        // per-row online softmax update (64 row-owner threads)
        if (tid < 64) {
            int r = tid;
            float mold = sM[r];
            float mt = mold;
#pragma unroll 8
            for (int j = 0; j < 64; j++) mt = fmaxf(mt, sP[r * PADP + j]);
            float corr = expf(mold - mt);
            float lsum = 0.f;
#pragma unroll 8
            for (int j = 0; j < 64; j++) {
                float p = expf(sP[r * PADP + j] - mt);
                sP[r * PADP + j] = p;
                lsum += p;
            }
            sM[r] = mt;
            sL[r] = sL[r] * corr + lsum;
            sC[r] = corr;
        }
        __syncthreads();

        // rescale accumulators, then O += P @ V
#pragma unroll
        for (int i = 0; i < 4; i++) {
            float cr = sC[ty * 4 + i];
#pragma unroll
            for (int j = 0; j < 4; j++) acc[i][j] *= cr;
        }
#pragma unroll 8
        for (int k = 0; k < 64; k++) {
            float pv[4];
#pragma unroll
            for (int i = 0; i < 4; i++) pv[i] = sP[(ty * 4 + i) * PADP + k];
            float4 vv = *(const float4*)&sV[k * PADT + tx * 4];
            float va[4] = {vv.x, vv.y, vv.z, vv.w};
#pragma unroll
            for (int i = 0; i < 4; i++)
#pragma unroll
                for (int j = 0; j < 4; j++)
                    acc[i][j] += pv[i] * va[j];
        }
        __syncthreads();
    }

    float* Ob = O + ((size_t)b * LQ + m0) * DIMC + h * HD;
#pragma unroll
    for (int i = 0; i < 4; i++) {
        int r = ty * 4 + i;
        float inv = 1.f / sL[r];
#pragma unroll
        for (int j = 0; j < 4; j++)
            Ob[(size_t)r * DIMC + tx * 4 + j] = acc[i][j] * inv;
    }
}

// ---------------- launch ----------------
extern "C" void kernel_launch(void* const* d_in, const int* in_sizes, int n_in,
                              void* d_out, int out_size)
{
    const float* x      = (const float*)d_in[0];
    // d_in[1] = h, d_in[2] = w  (56/56, hardcoded)
    const float* conv_q = (const float*)d_in[3];
    const float* bnq_s  = (const float*)d_in[4];
    const float* bnq_b  = (const float*)d_in[5];
    const float* bnq_m  = (const float*)d_in[6];
    const float* bnq_v  = (const float*)d_in[7];
    const float* conv_k = (const float*)d_in[8];
    const float* bnk_s  = (const float*)d_in[9];
    const float* bnk_b  = (const float*)d_in[10];
    const float* bnk_m  = (const float*)d_in[11];
    const float* bnk_v  = (const float*)d_in[12];
    const float* conv_v = (const float*)d_in[13];
    const float* bnv_s  = (const float*)d_in[14];
    const float* bnv_b  = (const float*)d_in[15];
    const float* bnv_m  = (const float*)d_in[16];
    const float* bnv_v  = (const float*)d_in[17];
    const float* wq     = (const float*)d_in[18];
    const float* wk     = (const float*)d_in[19];
    const float* wv     = (const float*)d_in[20];
    const float* w_last = (const float*)d_in[21];
    const float* b_last = (const float*)d_in[22];

    float *qc, *kc, *vc, *qp, *kp, *vp, *ob;
    cudaGetSymbolAddress((void**)&qc, g_qc);
    cudaGetSymbolAddress((void**)&kc, g_kc);
    cudaGetSymbolAddress((void**)&vc, g_vc);
    cudaGetSymbolAddress((void**)&qp, g_qp);
    cudaGetSymbolAddress((void**)&kp, g_kp);
    cudaGetSymbolAddress((void**)&vp, g_vp);
    cudaGetSymbolAddress((void**)&ob, g_ob);

    // depthwise conv + BN
    {
        int totq = BATCH * LQ * DIMC;
        int totk = BATCH * LKV * DIMC;
        dwconv_bn_kernel<<<(totq + 255) / 256, 256>>>(x, conv_q, bnq_s, bnq_b, bnq_m, bnq_v, qc, 1, 56);
        dwconv_bn_kernel<<<(totk + 255) / 256, 256>>>(x, conv_k, bnk_s, bnk_b, bnk_m, bnk_v, kc, 2, 28);
        dwconv_bn_kernel<<<(totk + 255) / 256, 256>>>(x, conv_v, bnv_s, bnv_b, bnv_m, bnv_v, vc, 2, 28);
    }

    // projections: y = x @ W^T
    gemm128_xwT<<<dim3(DIMC / 128, (BATCH * LQ)  / 128), 256>>>(qc, wq, nullptr, qp, BATCH * LQ,  DIMC, DIMC);
    gemm128_xwT<<<dim3(DIMC / 128, (BATCH * LKV) / 128), 256>>>(kc, wk, nullptr, kp, BATCH * LKV, DIMC, DIMC);
    gemm128_xwT<<<dim3(DIMC / 128, (BATCH * LKV) / 128), 256>>>(vc, wv, nullptr, vp, BATCH * LKV, DIMC, DIMC);

    // attention
    cudaFuncSetAttribute(attn_kernel, cudaFuncAttributeMaxDynamicSharedMemorySize, ATTN_SMEM);
    attn_kernel<<<dim3(LQ / 64, HEADS, BATCH), 256, ATTN_SMEM>>>(qp, kp, vp, ob);

    // final projection + bias -> d_out
    gemm128_xwT<<<dim3(DIMC / 128, (BATCH * LQ) / 128), 256>>>(ob, w_last, b_last, (float*)d_out,
                                                               BATCH * LQ, DIMC, DIMC);
}

// round 4
// speedup vs baseline: 2.3399x; 2.3399x over previous
#include <cuda_runtime.h>
#include <math.h>
#include <stdint.h>

#define BATCH 8
#define DIMC 384
#define HEADS 6
#define HD 64
#define HIN 56
#define LQ 3136        // 56*56
#define LKV 784        // 28*28
#define EPS 1e-5f
#define SCALE 0.05103103630798288f   // 384^-0.5

// ---------------- scratch (device globals; no runtime allocation) ----------------
__device__ float g_qc[BATCH * LQ  * DIMC];
__device__ float g_kc[BATCH * LKV * DIMC];
__device__ float g_vc[BATCH * LKV * DIMC];
__device__ float g_qp[BATCH * LQ  * DIMC];
__device__ float g_kp[BATCH * LKV * DIMC];
__device__ float g_vp[BATCH * LKV * DIMC];
__device__ float g_ob[BATCH * LQ  * DIMC];

// ---------------- tf32 helpers ----------------
__device__ __forceinline__ uint32_t f2tf(float f) {
    uint32_t u;
    asm("cvt.rna.tf32.f32 %0, %1;" : "=r"(u) : "f"(f));
    return u;
}

__device__ __forceinline__ void mma_tf32(float c[4], const uint32_t a[4], const uint32_t b[2]) {
    asm volatile(
        "mma.sync.aligned.m16n8k8.row.col.f32.tf32.tf32.f32 "
        "{%0,%1,%2,%3}, {%4,%5,%6,%7}, {%8,%9}, {%0,%1,%2,%3};\n"
        : "+f"(c[0]), "+f"(c[1]), "+f"(c[2]), "+f"(c[3])
        : "r"(a[0]), "r"(a[1]), "r"(a[2]), "r"(a[3]), "r"(b[0]), "r"(b[1]));
}

// ---------------- depthwise 3x3 conv + BN (inference) ----------------
__global__ void dwconv_bn_kernel(const float* __restrict__ x,
                                 const float* __restrict__ wt,   // [C,1,3,3]
                                 const float* __restrict__ sc,
                                 const float* __restrict__ bb,
                                 const float* __restrict__ mn,
                                 const float* __restrict__ vr,
                                 float* __restrict__ out,
                                 int stride, int Hout)
{
    int idx = blockIdx.x * blockDim.x + threadIdx.x;
    int total = BATCH * Hout * Hout * DIMC;
    if (idx >= total) return;
    int c = idx % DIMC;
    int t = (idx / DIMC) % (Hout * Hout);
    int b = idx / (DIMC * Hout * Hout);
    int oy = t / Hout, ox = t % Hout;

    float acc = 0.f;
#pragma unroll
    for (int dy = 0; dy < 3; dy++) {
        int iy = oy * stride + dy - 1;
        if (iy < 0 || iy >= HIN) continue;
#pragma unroll
        for (int dx = 0; dx < 3; dx++) {
            int ix = ox * stride + dx - 1;
            if (ix < 0 || ix >= HIN) continue;
            acc += x[((size_t)b * LQ + iy * HIN + ix) * DIMC + c] * wt[c * 9 + dy * 3 + dx];
        }
    }
    float inv = rsqrtf(vr[c] + EPS);
    out[idx] = (acc - mn[c]) * inv * sc[c] + bb[c];
}

// ---------------- tf32 GEMM: Y[M,N] = X[M,K] @ W[N,K]^T (+bias) ----------------
// Block tile 128x128, BK=16, 256 threads (8 warps as 2m x 4n, warp tile 64x32).
// Requires M%128==0, N%128==0, K%16==0.
#define GSTRIDE 20   // smem row stride in words for 16 k-values (conflict-free fragment reads)

__global__ __launch_bounds__(256, 2)
void gemm_tf32(const float* __restrict__ X,
               const float* __restrict__ W,
               const float* __restrict__ bias,
               float* __restrict__ Y,
               int M, int N, int K)
{
    __shared__ uint32_t sA[2][128 * GSTRIDE];
    __shared__ uint32_t sB[2][128 * GSTRIDE];

    const int bm = blockIdx.y * 128;
    const int bn = blockIdx.x * 128;
    const int tid = threadIdx.x;
    const int lane = tid & 31;
    const int w = tid >> 5;
    const int g = lane >> 2;
    const int tig = lane & 3;
    const int wm = (w & 1) * 64;
    const int wn = (w >> 1) * 32;

    // global load mapping: 128 rows x 16 cols per stage
    const int lr = tid >> 1;
    const int lkb = (tid & 1) * 8;
    const float* Xp = X + (size_t)(bm + lr) * K + lkb;
    const float* Wp = W + (size_t)(bn + lr) * K + lkb;

    float acc[4][4][4];
#pragma unroll
    for (int i = 0; i < 4; i++)
#pragma unroll
        for (int j = 0; j < 4; j++)
#pragma unroll
            for (int q = 0; q < 4; q++) acc[i][j][q] = 0.f;

    const int nstage = K / 16;

    // stage 0 direct load
    {
        float4 x0 = *(const float4*)(Xp + 0);
        float4 x1 = *(const float4*)(Xp + 4);
        float4 w0 = *(const float4*)(Wp + 0);
        float4 w1 = *(const float4*)(Wp + 4);
        uint32_t* a = &sA[0][lr * GSTRIDE + lkb];
        uint32_t* bq = &sB[0][lr * GSTRIDE + lkb];
        a[0] = f2tf(x0.x); a[1] = f2tf(x0.y); a[2] = f2tf(x0.z); a[3] = f2tf(x0.w);
        a[4] = f2tf(x1.x); a[5] = f2tf(x1.y); a[6] = f2tf(x1.z); a[7] = f2tf(x1.w);
        bq[0] = f2tf(w0.x); bq[1] = f2tf(w0.y); bq[2] = f2tf(w0.z); bq[3] = f2tf(w0.w);
        bq[4] = f2tf(w1.x); bq[5] = f2tf(w1.y); bq[6] = f2tf(w1.z); bq[7] = f2tf(w1.w);
    }
    __syncthreads();

    for (int s = 0; s < nstage; s++) {
        const int p = s & 1;
        float4 x0, x1, w0, w1;
        if (s + 1 < nstage) {
            int k0 = (s + 1) * 16;
            x0 = *(const float4*)(Xp + k0);
            x1 = *(const float4*)(Xp + k0 + 4);
            w0 = *(const float4*)(Wp + k0);
            w1 = *(const float4*)(Wp + k0 + 4);
        }

        const uint32_t* A = sA[p];
        const uint32_t* B = sB[p];
#pragma unroll
        for (int kk = 0; kk < 16; kk += 8) {
            uint32_t af[4][4];
#pragma unroll
            for (int mf = 0; mf < 4; mf++) {
                int mb = wm + mf * 16;
                af[mf][0] = A[(mb + g) * GSTRIDE + kk + tig];
                af[mf][1] = A[(mb + 8 + g) * GSTRIDE + kk + tig];
                af[mf][2] = A[(mb + g) * GSTRIDE + kk + tig + 4];
                af[mf][3] = A[(mb + 8 + g) * GSTRIDE + kk + tig + 4];
            }
            uint32_t bf[4][2];
#pragma unroll
            for (int nf = 0; nf < 4; nf++) {
                int nb = wn + nf * 8;
                bf[nf][0] = B[(nb + g) * GSTRIDE + kk + tig];
                bf[nf][1] = B[(nb + g) * GSTRIDE + kk + tig + 4];
            }
#pragma unroll
            for (int mf = 0; mf < 4; mf++)
#pragma unroll
                for (int nf = 0; nf < 4; nf++)
                    mma_tf32(acc[mf][nf], af[mf], bf[nf]);
        }

        if (s + 1 < nstage) {
            uint32_t* a = &sA[1 - p][lr * GSTRIDE + lkb];
            uint32_t* bq = &sB[1 - p][lr * GSTRIDE + lkb];
            a[0] = f2tf(x0.x); a[1] = f2tf(x0.y); a[2] = f2tf(x0.z); a[3] = f2tf(x0.w);
            a[4] = f2tf(x1.x); a[5] = f2tf(x1.y); a[6] = f2tf(x1.z); a[7] = f2tf(x1.w);
            bq[0] = f2tf(w0.x); bq[1] = f2tf(w0.y); bq[2] = f2tf(w0.z); bq[3] = f2tf(w0.w);
            bq[4] = f2tf(w1.x); bq[5] = f2tf(w1.y); bq[6] = f2tf(w1.z); bq[7] = f2tf(w1.w);
            __syncthreads();
        }
    }

    // epilogue
#pragma unroll
    for (int mf = 0; mf < 4; mf++) {
        int r0 = bm + wm + mf * 16 + g;
#pragma unroll
        for (int nf = 0; nf < 4; nf++) {
            int c0 = bn + wn + nf * 8 + 2 * tig;
            float b0 = bias ? bias[c0] : 0.f;
            float b1 = bias ? bias[c0 + 1] : 0.f;
            Y[(size_t)r0 * N + c0]           = acc[mf][nf][0] + b0;
            Y[(size_t)r0 * N + c0 + 1]       = acc[mf][nf][1] + b1;
            Y[(size_t)(r0 + 8) * N + c0]     = acc[mf][nf][2] + b0;
            Y[(size_t)(r0 + 8) * N + c0 + 1] = acc[mf][nf][3] + b1;
        }
    }
}

// ---------------- tf32 flash attention ----------------
// 64 q-rows x 64 kv tile, 4 warps (each owns 16 q-rows), online softmax in registers.
// smem: sQ[64][68] (tf32), sKP[64][68] (K then reused for P), sV[64][72] (tf32).
#define SQ_STR 68
#define SV_STR 72
#define ATTN_SMEM_WORDS (64 * SQ_STR + 64 * SQ_STR + 64 * SV_STR)
#define ATTN_SMEM_BYTES (ATTN_SMEM_WORDS * 4)

__global__ __launch_bounds__(128, 3)
void attn_tf32(const float* __restrict__ Q,
               const float* __restrict__ K,
               const float* __restrict__ V,
               float* __restrict__ O)
{
    extern __shared__ uint32_t smem_u[];
    uint32_t* sQ  = smem_u;
    uint32_t* sKP = smem_u + 64 * SQ_STR;
    uint32_t* sV  = sKP + 64 * SQ_STR;

    const int b = blockIdx.z, h = blockIdx.y;
    const int m0 = blockIdx.x * 64;
    const int tid = threadIdx.x;
    const int lane = tid & 31;
    const int w = tid >> 5;
    const int g = lane >> 2;
    const int tig = lane & 3;
    const int wrow = w * 16;  // warp's q-row base within tile

    // load Q tile (64x64) -> tf32 smem
    const float* Qb = Q + ((size_t)b * LQ + m0) * DIMC + h * HD;
    for (int i = tid; i < 64 * 16; i += 128) {
        int r = i >> 4, c4 = (i & 15) * 4;
        float4 qv = *(const float4*)(Qb + (size_t)r * DIMC + c4);
        uint32_t* dst = &sQ[r * SQ_STR + c4];
        dst[0] = f2tf(qv.x); dst[1] = f2tf(qv.y); dst[2] = f2tf(qv.z); dst[3] = f2tf(qv.w);
    }

    float m2[2] = {-1e30f, -1e30f};
    float lsum[2] = {0.f, 0.f};
    float oacc[8][4];
#pragma unroll
    for (int i = 0; i < 8; i++)
#pragma unroll
        for (int j = 0; j < 4; j++) oacc[i][j] = 0.f;

    __syncthreads();

    const float c1 = SCALE * 1.4426950408889634f;

    for (int n0 = 0; n0 < LKV; n0 += 64) {
        const int nv = (LKV - n0 < 64) ? (LKV - n0) : 64;
        const float* Kb = K + ((size_t)b * LKV + n0) * DIMC + h * HD;
        const float* Vb = V + ((size_t)b * LKV + n0) * DIMC + h * HD;

        // load K (into sKP) and V (into sV), tf32, zero-pad invalid rows
        for (int i = tid; i < 64 * 16; i += 128) {
            int r = i >> 4, c4 = (i & 15) * 4;
            float4 kv, vv;
            if (r < nv) {
                kv = *(const float4*)(Kb + (size_t)r * DIMC + c4);
                vv = *(const float4*)(Vb + (size_t)r * DIMC + c4);
            } else {
                kv = make_float4(0.f, 0.f, 0.f, 0.f);
                vv = kv;
            }
            uint32_t* dk = &sKP[r * SQ_STR + c4];
            dk[0] = f2tf(kv.x); dk[1] = f2tf(kv.y); dk[2] = f2tf(kv.z); dk[3] = f2tf(kv.w);
            uint32_t* dv = &sV[r * SV_STR + c4];
            dv[0] = f2tf(vv.x); dv[1] = f2tf(vv.y); dv[2] = f2tf(vv.z); dv[3] = f2tf(vv.w);
        }
        __syncthreads();

        // ---- S = Q @ K^T ----
        float sacc[8][4];
#pragma unroll
        for (int i = 0; i < 8; i++)
#pragma unroll
            for (int j = 0; j < 4; j++) sacc[i][j] = 0.f;

#pragma unroll
        for (int kk = 0; kk < 64; kk += 8) {
            uint32_t aq[4];
            aq[0] = sQ[(wrow + g) * SQ_STR + kk + tig];
            aq[1] = sQ[(wrow + 8 + g) * SQ_STR + kk + tig];
            aq[2] = sQ[(wrow + g) * SQ_STR + kk + tig + 4];
            aq[3] = sQ[(wrow + 8 + g) * SQ_STR + kk + tig + 4];
#pragma unroll
            for (int nf = 0; nf < 8; nf++) {
                uint32_t bk[2];
                bk[0] = sKP[(nf * 8 + g) * SQ_STR + kk + tig];
                bk[1] = sKP[(nf * 8 + g) * SQ_STR + kk + tig + 4];
                mma_tf32(sacc[nf], aq, bk);
            }
        }
        __syncthreads();  // all warps done reading K before P overwrite

        // ---- online softmax (register, base-2 domain) ----
        float mt[2] = {-1e30f, -1e30f};
#pragma unroll
        for (int nf = 0; nf < 8; nf++) {
#pragma unroll
            for (int c = 0; c < 4; c++) {
                int col = nf * 8 + 2 * tig + (c & 1);
                float lg = (n0 + col < LKV) ? sacc[nf][c] * c1 : -1e30f;
                sacc[nf][c] = lg;
                int rr = c >> 1;
                mt[rr] = fmaxf(mt[rr], lg);
            }
        }
#pragma unroll
        for (int rr = 0; rr < 2; rr++) {
            mt[rr] = fmaxf(mt[rr], __shfl_xor_sync(0xffffffffu, mt[rr], 1));
            mt[rr] = fmaxf(mt[rr], __shfl_xor_sync(0xffffffffu, mt[rr], 2));
        }
        float corr[2];
#pragma unroll
        for (int rr = 0; rr < 2; rr++) {
            float mn = fmaxf(m2[rr], mt[rr]);
            corr[rr] = exp2f(m2[rr] - mn);
            m2[rr] = mn;
        }
        float rsum[2] = {0.f, 0.f};
#pragma unroll
        for (int nf = 0; nf < 8; nf++) {
#pragma unroll
            for (int c = 0; c < 4; c++) {
                int rr = c >> 1;
                float p = exp2f(sacc[nf][c] - m2[rr]);
                sacc[nf][c] = p;
                rsum[rr] += p;
            }
        }
#pragma unroll
        for (int rr = 0; rr < 2; rr++) {
            rsum[rr] += __shfl_xor_sync(0xffffffffu, rsum[rr], 1);
            rsum[rr] += __shfl_xor_sync(0xffffffffu, rsum[rr], 2);
            lsum[rr] = lsum[rr] * corr[rr] + rsum[rr];
        }
        // rescale O accumulators
#pragma unroll
        for (int nf = 0; nf < 8; nf++) {
            oacc[nf][0] *= corr[0];
            oacc[nf][1] *= corr[0];
            oacc[nf][2] *= corr[1];
            oacc[nf][3] *= corr[1];
        }

        // ---- store P (tf32) into sKP ----
        {
            int rb0 = (wrow + g) * SQ_STR;
            int rb1 = (wrow + 8 + g) * SQ_STR;
#pragma unroll
            for (int nf = 0; nf < 8; nf++) {
                int cb = nf * 8 + 2 * tig;
                sKP[rb0 + cb]     = f2tf(sacc[nf][0]);
                sKP[rb0 + cb + 1] = f2tf(sacc[nf][1]);
                sKP[rb1 + cb]     = f2tf(sacc[nf][2]);
                sKP[rb1 + cb + 1] = f2tf(sacc[nf][3]);
            }
        }
        __syncthreads();

        // ---- O += P @ V ----
#pragma unroll
        for (int kk = 0; kk < 64; kk += 8) {
            uint32_t ap[4];
            ap[0] = sKP[(wrow + g) * SQ_STR + kk + tig];
            ap[1] = sKP[(wrow + 8 + g) * SQ_STR + kk + tig];
            ap[2] = sKP[(wrow + g) * SQ_STR + kk + tig + 4];
            ap[3] = sKP[(wrow + 8 + g) * SQ_STR + kk + tig + 4];
#pragma unroll
            for (int nf = 0; nf < 8; nf++) {
                uint32_t bv[2];
                bv[0] = sV[(kk + tig) * SV_STR + nf * 8 + g];
                bv[1] = sV[(kk + tig + 4) * SV_STR + nf * 8 + g];
                mma_tf32(oacc[nf], ap, bv);
            }
        }
        __syncthreads();  // before next tile overwrites sKP/sV
    }

    // epilogue: O / l
    float inv0 = 1.f / lsum[0];
    float inv1 = 1.f / lsum[1];
    float* Ob = O + ((size_t)b * LQ + m0) * DIMC + h * HD;
    size_t r0 = (size_t)(wrow + g) * DIMC;
    size_t r1 = (size_t)(wrow + 8 + g) * DIMC;
#pragma unroll
    for (int nf = 0; nf < 8; nf++) {
        int cb = nf * 8 + 2 * tig;
        Ob[r0 + cb]     = oacc[nf][0] * inv0;
        Ob[r0 + cb + 1] = oacc[nf][1] * inv0;
        Ob[r1 + cb]     = oacc[nf][2] * inv1;
        Ob[r1 + cb + 1] = oacc[nf][3] * inv1;
    }
}

// ---------------- launch ----------------
extern "C" void kernel_launch(void* const* d_in, const int* in_sizes, int n_in,
                              void* d_out, int out_size)
{
    const float* x      = (const float*)d_in[0];
    const float* conv_q = (const float*)d_in[3];
    const float* bnq_s  = (const float*)d_in[4];
    const float* bnq_b  = (const float*)d_in[5];
    const float* bnq_m  = (const float*)d_in[6];
    const float* bnq_v  = (const float*)d_in[7];
    const float* conv_k = (const float*)d_in[8];
    const float* bnk_s  = (const float*)d_in[9];
    const float* bnk_b  = (const float*)d_in[10];
    const float* bnk_m  = (const float*)d_in[11];
    const float* bnk_v  = (const float*)d_in[12];
    const float* conv_v = (const float*)d_in[13];
    const float* bnv_s  = (const float*)d_in[14];
    const float* bnv_b  = (const float*)d_in[15];
    const float* bnv_m  = (const float*)d_in[16];
    const float* bnv_v  = (const float*)d_in[17];
    const float* wq     = (const float*)d_in[18];
    const float* wk     = (const float*)d_in[19];
    const float* wv     = (const float*)d_in[20];
    const float* w_last = (const float*)d_in[21];
    const float* b_last = (const float*)d_in[22];

    float *qc, *kc, *vc, *qp, *kp, *vp, *ob;
    cudaGetSymbolAddress((void**)&qc, g_qc);
    cudaGetSymbolAddress((void**)&kc, g_kc);
    cudaGetSymbolAddress((void**)&vc, g_vc);
    cudaGetSymbolAddress((void**)&qp, g_qp);
    cudaGetSymbolAddress((void**)&kp, g_kp);
    cudaGetSymbolAddress((void**)&vp, g_vp);
    cudaGetSymbolAddress((void**)&ob, g_ob);

    // depthwise conv + BN
    {
        int totq = BATCH * LQ * DIMC;
        int totk = BATCH * LKV * DIMC;
        dwconv_bn_kernel<<<(totq + 255) / 256, 256>>>(x, conv_q, bnq_s, bnq_b, bnq_m, bnq_v, qc, 1, 56);
        dwconv_bn_kernel<<<(totk + 255) / 256, 256>>>(x, conv_k, bnk_s, bnk_b, bnk_m, bnk_v, kc, 2, 28);
        dwconv_bn_kernel<<<(totk + 255) / 256, 256>>>(x, conv_v, bnv_s, bnv_b, bnv_m, bnv_v, vc, 2, 28);
    }

    // projections: y = x @ W^T (tf32 tensor cores)
    gemm_tf32<<<dim3(DIMC / 128, (BATCH * LQ)  / 128), 256>>>(qc, wq, nullptr, qp, BATCH * LQ,  DIMC, DIMC);
    gemm_tf32<<<dim3(DIMC / 128, (BATCH * LKV) / 128), 256>>>(kc, wk, nullptr, kp, BATCH * LKV, DIMC, DIMC);
    gemm_tf32<<<dim3(DIMC / 128, (BATCH * LKV) / 128), 256>>>(vc, wv, nullptr, vp, BATCH * LKV, DIMC, DIMC);

    // attention (tf32 tensor cores)
    cudaFuncSetAttribute(attn_tf32, cudaFuncAttributeMaxDynamicSharedMemorySize, ATTN_SMEM_BYTES);
    attn_tf32<<<dim3(LQ / 64, HEADS, BATCH), 128, ATTN_SMEM_BYTES>>>(qp, kp, vp, ob);

    // final projection + bias -> d_out
    gemm_tf32<<<dim3(DIMC / 128, (BATCH * LQ) / 128), 256>>>(ob, w_last, b_last, (float*)d_out,
                                                             BATCH * LQ, DIMC, DIMC);
}